// round 8
// baseline (speedup 1.0000x reference)
#include <cuda_runtime.h>
#include <cuda_bf16.h>

// Causal cumulative normalization along frames.
// THREE consecutive rows per warp, 128-frame chunks (1 float4/lane/row),
// 1-chunk software prefetch, warp shuffle scan with register carries.
// Grid sized to exactly ONE wave: 1366 blocks of 128 thr @ 10 blocks/SM.
// Rows B/C addressed via immediate offsets from row A base (reg savings).
// Division-free: out = (x*c - s) * rsqrt(c*(q + eps*c) - s*s).

#define EPSV 1e-4f

constexpr int FRAMES = 4000;
constexpr int F4     = FRAMES / 4;   // 1000 float4 per row
constexpr int NFULL  = 31;           // 31 * 128 = 3968 frames
// tail: 32 frames (3968..3999)

__device__ __forceinline__ void process128(float4 cv, float cbase, int lane,
                                           float& carry_s, float& carry_q,
                                           float4* outp, bool wr) {
    // per-lane inclusive prefixes over 4 elements
    float s0 = cv.x;
    float s1 = s0 + cv.y;
    float s2 = s1 + cv.z;
    float s3 = s2 + cv.w;
    float q0 = cv.x * cv.x;
    float q1 = fmaf(cv.y, cv.y, q0);
    float q2 = fmaf(cv.z, cv.z, q1);
    float q3 = fmaf(cv.w, cv.w, q2);

    // warp inclusive scan of lane totals
    float ts = s3, tq = q3;
    #pragma unroll
    for (int off = 1; off < 32; off <<= 1) {
        float as = __shfl_up_sync(0xffffffffu, ts, off);
        float aq = __shfl_up_sync(0xffffffffu, tq, off);
        if (lane >= off) { ts += as; tq += aq; }
    }

    float bs = carry_s + (ts - s3);   // exclusive lane base + carry
    float bq = carry_q + (tq - q3);
    carry_s += __shfl_sync(0xffffffffu, ts, 31);
    carry_q += __shfl_sync(0xffffffffu, tq, 31);

    float4 o;
    {
        float c = cbase;
        float s = bs + s0, q = bq + q0;
        float u = fmaf(EPSV, c, q);
        float r = fmaf(c, u, -s * s);
        o.x = fmaf(cv.x, c, -s) * rsqrtf(r);
    }
    {
        float c = cbase + 1.0f;
        float s = bs + s1, q = bq + q1;
        float u = fmaf(EPSV, c, q);
        float r = fmaf(c, u, -s * s);
        o.y = fmaf(cv.y, c, -s) * rsqrtf(r);
    }
    {
        float c = cbase + 2.0f;
        float s = bs + s2, q = bq + q2;
        float u = fmaf(EPSV, c, q);
        float r = fmaf(c, u, -s * s);
        o.z = fmaf(cv.z, c, -s) * rsqrtf(r);
    }
    {
        float c = cbase + 3.0f;
        float s = bs + s3, q = bq + q3;
        float u = fmaf(EPSV, c, q);
        float r = fmaf(c, u, -s * s);
        o.w = fmaf(cv.w, c, -s) * rsqrtf(r);
    }
    if (wr) __stcs(outp, o);
}

__device__ __forceinline__ void tail32(const float* xr, float* outr, int lane,
                                       float carry_s, float carry_q, bool wr) {
    int base = NFULL * 128 + lane;   // 3968 + lane
    float xval = __ldcs(xr + base);
    float ts = xval, tq = xval * xval;
    #pragma unroll
    for (int off = 1; off < 32; off <<= 1) {
        float as = __shfl_up_sync(0xffffffffu, ts, off);
        float aq = __shfl_up_sync(0xffffffffu, tq, off);
        if (lane >= off) { ts += as; tq += aq; }
    }
    float c = (float)(base + 1);
    float s = carry_s + ts;
    float q = carry_q + tq;
    float u = fmaf(EPSV, c, q);
    float r = fmaf(c, u, -s * s);
    float o = fmaf(xval, c, -s) * rsqrtf(r);
    if (wr) __stcs(outr + base, o);
}

__global__ __launch_bounds__(128, 10)
void cumnorm_kernel(const float* __restrict__ x, float* __restrict__ out, int rows) {
    int gw   = (blockIdx.x * blockDim.x + threadIdx.x) >> 5;
    int lane = threadIdx.x & 31;

    long long r0 = 3LL * gw;
    if (r0 >= rows) return;
    bool v1 = (r0 + 1) < rows;
    bool v2 = (r0 + 2) < rows;
    int d1 = v1 ? F4     : 0;   // clamp invalid rows onto row A (loads only)
    int d2 = v2 ? 2 * F4 : 0;

    const float4* __restrict__ xa = (const float4*)(x + r0 * FRAMES);
    float4*       __restrict__ oa = (float4*)(out + r0 * FRAMES);

    float cs0 = 0.0f, cq0 = 0.0f;
    float cs1 = 0.0f, cq1 = 0.0f;
    float cs2 = 0.0f, cq2 = 0.0f;

    float clane = (float)(lane * 4 + 1);

    // prefetch first 128-frame chunk of each row
    float4 a = __ldcs(xa + lane);
    float4 b = __ldcs(xa + d1 + lane);
    float4 c = __ldcs(xa + d2 + lane);

    #pragma unroll 1
    for (int it = 0; it < NFULL; ++it) {
        float4 ca = a, cb = b, cc = c;
        if (it + 1 < NFULL) {
            int nb = (it + 1) * 32 + lane;
            a = __ldcs(xa + nb);
            b = __ldcs(xa + d1 + nb);
            c = __ldcs(xa + d2 + nb);
        }
        float cbase = (float)(it * 128) + clane;
        process128(ca, cbase, lane, cs0, cq0, oa + it * 32 + lane,      true);
        process128(cb, cbase, lane, cs1, cq1, oa + d1 + it * 32 + lane, v1);
        process128(cc, cbase, lane, cs2, cq2, oa + d2 + it * 32 + lane, v2);
    }

    // 32-frame tails (frames 3968..3999)
    tail32((const float*)xa,            (float*)oa,            lane, cs0, cq0, true);
    tail32((const float*)(xa + d1),     (float*)(oa + d1),     lane, cs1, cq1, v1);
    tail32((const float*)(xa + d2),     (float*)(oa + d2),     lane, cs2, cq2, v2);
}

extern "C" void kernel_launch(void* const* d_in, const int* in_sizes, int n_in,
                              void* d_out, int out_size) {
    const float* x = (const float*)d_in[0];
    float* out = (float*)d_out;
    int rows = in_sizes[0] / FRAMES;          // 32*512 = 16384

    int warps  = (rows + 2) / 3;              // 3 rows per warp -> 5462
    constexpr int WARPS_PER_BLOCK = 4;        // 128-thread blocks
    int blocks = (warps + WARPS_PER_BLOCK - 1) / WARPS_PER_BLOCK;  // 1366 -> one wave
    cumnorm_kernel<<<blocks, WARPS_PER_BLOCK * 32>>>(x, out, rows);
}

// round 10
// speedup vs baseline: 1.0369x; 1.0369x over previous
#include <cuda_runtime.h>
#include <cuda_bf16.h>

// Causal cumulative normalization along frames.
// FOUR consecutive rows per warp (rows % 4 == 0 for this problem), 128-frame
// chunks (1 float4/lane/row), 1-chunk software prefetch, warp shuffle scan
// with register carries. Rows B/C/D addressed via COMPILE-TIME immediate
// offsets (F4, 2*F4, 3*F4) from row A's base pointer -> no extra address math.
// Grid = 1024 blocks of 128 thr @ 8 blocks/SM -> exactly ONE perfectly
// balanced wave (every warp does exactly 4 rows).
// Division-free: out = (x*c - s) * rsqrt(c*(q + eps*c) - s*s).

#define EPSV 1e-4f

constexpr int FRAMES = 4000;
constexpr int F4     = FRAMES / 4;   // 1000 float4 per row
constexpr int NFULL  = 31;           // 31 * 128 = 3968 frames
// tail: 32 frames (3968..3999)

__device__ __forceinline__ void process128(float4 cv, float cbase, int lane,
                                           float& carry_s, float& carry_q,
                                           float4* outp) {
    // per-lane inclusive prefixes over 4 elements
    float s0 = cv.x;
    float s1 = s0 + cv.y;
    float s2 = s1 + cv.z;
    float s3 = s2 + cv.w;
    float q0 = cv.x * cv.x;
    float q1 = fmaf(cv.y, cv.y, q0);
    float q2 = fmaf(cv.z, cv.z, q1);
    float q3 = fmaf(cv.w, cv.w, q2);

    // warp inclusive scan of lane totals
    float ts = s3, tq = q3;
    #pragma unroll
    for (int off = 1; off < 32; off <<= 1) {
        float as = __shfl_up_sync(0xffffffffu, ts, off);
        float aq = __shfl_up_sync(0xffffffffu, tq, off);
        if (lane >= off) { ts += as; tq += aq; }
    }

    float bs = carry_s + (ts - s3);   // exclusive lane base + carry
    float bq = carry_q + (tq - q3);
    carry_s += __shfl_sync(0xffffffffu, ts, 31);
    carry_q += __shfl_sync(0xffffffffu, tq, 31);

    float4 o;
    {
        float c = cbase;
        float s = bs + s0, q = bq + q0;
        float u = fmaf(EPSV, c, q);
        float r = fmaf(c, u, -s * s);
        o.x = fmaf(cv.x, c, -s) * rsqrtf(r);
    }
    {
        float c = cbase + 1.0f;
        float s = bs + s1, q = bq + q1;
        float u = fmaf(EPSV, c, q);
        float r = fmaf(c, u, -s * s);
        o.y = fmaf(cv.y, c, -s) * rsqrtf(r);
    }
    {
        float c = cbase + 2.0f;
        float s = bs + s2, q = bq + q2;
        float u = fmaf(EPSV, c, q);
        float r = fmaf(c, u, -s * s);
        o.z = fmaf(cv.z, c, -s) * rsqrtf(r);
    }
    {
        float c = cbase + 3.0f;
        float s = bs + s3, q = bq + q3;
        float u = fmaf(EPSV, c, q);
        float r = fmaf(c, u, -s * s);
        o.w = fmaf(cv.w, c, -s) * rsqrtf(r);
    }
    __stcs(outp, o);
}

__device__ __forceinline__ void tail32(const float* xr, float* outr, int lane,
                                       float carry_s, float carry_q) {
    int base = NFULL * 128 + lane;   // 3968 + lane
    float xval = __ldcs(xr + base);
    float ts = xval, tq = xval * xval;
    #pragma unroll
    for (int off = 1; off < 32; off <<= 1) {
        float as = __shfl_up_sync(0xffffffffu, ts, off);
        float aq = __shfl_up_sync(0xffffffffu, tq, off);
        if (lane >= off) { ts += as; tq += aq; }
    }
    float c = (float)(base + 1);
    float s = carry_s + ts;
    float q = carry_q + tq;
    float u = fmaf(EPSV, c, q);
    float r = fmaf(c, u, -s * s);
    __stcs(outr + base, fmaf(xval, c, -s) * rsqrtf(r));
}

__global__ __launch_bounds__(128, 8)
void cumnorm_kernel(const float* __restrict__ x, float* __restrict__ out, int groups) {
    int gw   = (blockIdx.x * blockDim.x + threadIdx.x) >> 5;
    int lane = threadIdx.x & 31;
    if (gw >= groups) return;

    // one base pointer; rows B/C/D at immediate float4 offsets F4, 2*F4, 3*F4
    const float4* __restrict__ xa = (const float4*)(x + (long long)(4 * gw) * FRAMES);
    float4*       __restrict__ oa = (float4*)(out + (long long)(4 * gw) * FRAMES);

    float cs0 = 0.0f, cq0 = 0.0f;
    float cs1 = 0.0f, cq1 = 0.0f;
    float cs2 = 0.0f, cq2 = 0.0f;
    float cs3 = 0.0f, cq3 = 0.0f;

    float clane = (float)(lane * 4 + 1);

    // prefetch first 128-frame chunk of each row
    float4 a = __ldcs(xa + lane);
    float4 b = __ldcs(xa + F4 + lane);
    float4 c = __ldcs(xa + 2 * F4 + lane);
    float4 d = __ldcs(xa + 3 * F4 + lane);

    #pragma unroll 1
    for (int it = 0; it < NFULL; ++it) {
        float4 ca = a, cb = b, cc = c, cd = d;
        if (it + 1 < NFULL) {
            int nb = (it + 1) * 32 + lane;
            a = __ldcs(xa + nb);
            b = __ldcs(xa + F4 + nb);
            c = __ldcs(xa + 2 * F4 + nb);
            d = __ldcs(xa + 3 * F4 + nb);
        }
        float cbase = (float)(it * 128) + clane;
        int ob = it * 32 + lane;
        process128(ca, cbase, lane, cs0, cq0, oa + ob);
        process128(cb, cbase, lane, cs1, cq1, oa + F4 + ob);
        process128(cc, cbase, lane, cs2, cq2, oa + 2 * F4 + ob);
        process128(cd, cbase, lane, cs3, cq3, oa + 3 * F4 + ob);
    }

    // 32-frame tails (frames 3968..3999)
    const float* xs = (const float*)xa;
    float*       os = (float*)oa;
    tail32(xs,              os,              lane, cs0, cq0);
    tail32(xs + FRAMES,     os + FRAMES,     lane, cs1, cq1);
    tail32(xs + 2 * FRAMES, os + 2 * FRAMES, lane, cs2, cq2);
    tail32(xs + 3 * FRAMES, os + 3 * FRAMES, lane, cs3, cq3);
}

extern "C" void kernel_launch(void* const* d_in, const int* in_sizes, int n_in,
                              void* d_out, int out_size) {
    const float* x = (const float*)d_in[0];
    float* out = (float*)d_out;
    int rows   = in_sizes[0] / FRAMES;   // 32*512 = 16384 (divisible by 4)
    int groups = rows / 4;               // 4096 warps

    constexpr int WARPS_PER_BLOCK = 4;   // 128-thread blocks
    int blocks = (groups + WARPS_PER_BLOCK - 1) / WARPS_PER_BLOCK;  // 1024 -> one wave
    cumnorm_kernel<<<blocks, WARPS_PER_BLOCK * 32>>>(x, out, groups);
}

// round 11
// speedup vs baseline: 1.1586x; 1.1173x over previous
#include <cuda_runtime.h>
#include <cuda_bf16.h>

// Causal cumulative normalization along frames.
// TWO consecutive rows per warp (row B at immediate offset), 256-frame chunks
// with 256-bit (v8.f32) global loads/stores: one lane = 8 contiguous frames,
// ONE warp scan ladder per 256 frames. 1-chunk software prefetch.
// Grid 2048 blocks x 128 thr (the shape with the small e2e-vs-kernel gap).
// Division-free: out = (x*c - s) * rsqrt(c*(q + eps*c) - s*s).

#define EPSV 1e-4f

constexpr int FRAMES   = 4000;
constexpr int NFULL256 = 15;   // 15*256 = 3840; then 128-frame chunk; then 32 tail

struct f8 { float v[8]; };

__device__ __forceinline__ f8 ldg256cs(const float* p) {
    f8 r;
    asm volatile("ld.global.cs.v8.f32 {%0,%1,%2,%3,%4,%5,%6,%7}, [%8];"
                 : "=f"(r.v[0]), "=f"(r.v[1]), "=f"(r.v[2]), "=f"(r.v[3]),
                   "=f"(r.v[4]), "=f"(r.v[5]), "=f"(r.v[6]), "=f"(r.v[7])
                 : "l"(p));
    return r;
}

__device__ __forceinline__ void stg256cs(float* p, const f8& r) {
    asm volatile("st.global.cs.v8.f32 [%0], {%1,%2,%3,%4,%5,%6,%7,%8};"
                 :: "l"(p),
                    "f"(r.v[0]), "f"(r.v[1]), "f"(r.v[2]), "f"(r.v[3]),
                    "f"(r.v[4]), "f"(r.v[5]), "f"(r.v[6]), "f"(r.v[7])
                 : "memory");
}

// 256 frames per warp: lane covers 8 contiguous frames, one scan ladder.
__device__ __forceinline__ void process256(const f8& cv, float cbase, int lane,
                                           float& carry_s, float& carry_q,
                                           float* outp) {
    float s[8], q[8];
    s[0] = cv.v[0];
    q[0] = cv.v[0] * cv.v[0];
    #pragma unroll
    for (int i = 1; i < 8; ++i) {
        s[i] = s[i - 1] + cv.v[i];
        q[i] = fmaf(cv.v[i], cv.v[i], q[i - 1]);
    }

    float ts = s[7], tq = q[7];
    #pragma unroll
    for (int off = 1; off < 32; off <<= 1) {
        float as = __shfl_up_sync(0xffffffffu, ts, off);
        float aq = __shfl_up_sync(0xffffffffu, tq, off);
        if (lane >= off) { ts += as; tq += aq; }
    }

    float bs = carry_s + (ts - s[7]);   // exclusive lane base + carry
    float bq = carry_q + (tq - q[7]);
    carry_s += __shfl_sync(0xffffffffu, ts, 31);
    carry_q += __shfl_sync(0xffffffffu, tq, 31);

    f8 o;
    #pragma unroll
    for (int i = 0; i < 8; ++i) {
        float c  = cbase + (float)i;
        float ss = bs + s[i];
        float qq = bq + q[i];
        float u  = fmaf(EPSV, c, qq);
        float r  = fmaf(c, u, -ss * ss);
        o.v[i]   = fmaf(cv.v[i], c, -ss) * rsqrtf(r);
    }
    stg256cs(outp, o);
}

// 128 frames, float4 per lane (trailing chunk)
__device__ __forceinline__ void process128(float4 cv, float cbase, int lane,
                                           float& carry_s, float& carry_q,
                                           float4* outp) {
    float s0 = cv.x;
    float s1 = s0 + cv.y;
    float s2 = s1 + cv.z;
    float s3 = s2 + cv.w;
    float q0 = cv.x * cv.x;
    float q1 = fmaf(cv.y, cv.y, q0);
    float q2 = fmaf(cv.z, cv.z, q1);
    float q3 = fmaf(cv.w, cv.w, q2);

    float ts = s3, tq = q3;
    #pragma unroll
    for (int off = 1; off < 32; off <<= 1) {
        float as = __shfl_up_sync(0xffffffffu, ts, off);
        float aq = __shfl_up_sync(0xffffffffu, tq, off);
        if (lane >= off) { ts += as; tq += aq; }
    }

    float bs = carry_s + (ts - s3);
    float bq = carry_q + (tq - q3);
    carry_s += __shfl_sync(0xffffffffu, ts, 31);
    carry_q += __shfl_sync(0xffffffffu, tq, 31);

    float4 o;
    {
        float c = cbase;
        float s = bs + s0, q = bq + q0;
        float u = fmaf(EPSV, c, q);
        float r = fmaf(c, u, -s * s);
        o.x = fmaf(cv.x, c, -s) * rsqrtf(r);
    }
    {
        float c = cbase + 1.0f;
        float s = bs + s1, q = bq + q1;
        float u = fmaf(EPSV, c, q);
        float r = fmaf(c, u, -s * s);
        o.y = fmaf(cv.y, c, -s) * rsqrtf(r);
    }
    {
        float c = cbase + 2.0f;
        float s = bs + s2, q = bq + q2;
        float u = fmaf(EPSV, c, q);
        float r = fmaf(c, u, -s * s);
        o.z = fmaf(cv.z, c, -s) * rsqrtf(r);
    }
    {
        float c = cbase + 3.0f;
        float s = bs + s3, q = bq + q3;
        float u = fmaf(EPSV, c, q);
        float r = fmaf(c, u, -s * s);
        o.w = fmaf(cv.w, c, -s) * rsqrtf(r);
    }
    __stcs(outp, o);
}

__device__ __forceinline__ void tail32(const float* xr, float* outr, int lane,
                                       float carry_s, float carry_q) {
    int base = 3968 + lane;
    float xval = __ldcs(xr + base);
    float ts = xval, tq = xval * xval;
    #pragma unroll
    for (int off = 1; off < 32; off <<= 1) {
        float as = __shfl_up_sync(0xffffffffu, ts, off);
        float aq = __shfl_up_sync(0xffffffffu, tq, off);
        if (lane >= off) { ts += as; tq += aq; }
    }
    float c = (float)(base + 1);
    float s = carry_s + ts;
    float q = carry_q + tq;
    float u = fmaf(EPSV, c, q);
    float r = fmaf(c, u, -s * s);
    __stcs(outr + base, fmaf(xval, c, -s) * rsqrtf(r));
}

__global__ __launch_bounds__(128, 7)
void cumnorm_kernel(const float* __restrict__ x, float* __restrict__ out, int pairs) {
    int gw   = (blockIdx.x * blockDim.x + threadIdx.x) >> 5;
    int lane = threadIdx.x & 31;
    if (gw >= pairs) return;

    const float* __restrict__ xs = x   + (long long)(2 * gw) * FRAMES;
    float*       __restrict__ os = out + (long long)(2 * gw) * FRAMES;

    float csa = 0.0f, cqa = 0.0f;   // carries row A
    float csb = 0.0f, cqb = 0.0f;   // carries row B

    float clane = (float)(lane * 8 + 1);
    int loff = lane * 8;

    // prefetch first 256-frame chunk of both rows
    f8 a = ldg256cs(xs + loff);
    f8 b = ldg256cs(xs + FRAMES + loff);

    // trailing 128-frame chunk buffers (filled during last main iteration)
    float4 a4, b4;

    #pragma unroll 1
    for (int it = 0; it < NFULL256; ++it) {
        f8 ca = a, cb = b;
        if (it + 1 < NFULL256) {
            int nb = (it + 1) * 256 + loff;
            a = ldg256cs(xs + nb);
            b = ldg256cs(xs + FRAMES + nb);
        } else {
            a4 = __ldcs((const float4*)(xs + 3840) + lane);
            b4 = __ldcs((const float4*)(xs + FRAMES + 3840) + lane);
        }
        float cbase = (float)(it * 256) + clane;
        int ob = it * 256 + loff;
        process256(ca, cbase, lane, csa, cqa, os + ob);
        process256(cb, cbase, lane, csb, cqb, os + FRAMES + ob);
    }

    // trailing 128-frame chunk (frames 3840..3967)
    float c4 = 3840.0f + (float)(lane * 4 + 1);
    process128(a4, c4, lane, csa, cqa, (float4*)(os + 3840) + lane);
    process128(b4, c4, lane, csb, cqb, (float4*)(os + FRAMES + 3840) + lane);

    // 32-frame tails (frames 3968..3999)
    tail32(xs,          os,          lane, csa, cqa);
    tail32(xs + FRAMES, os + FRAMES, lane, csb, cqb);
}

extern "C" void kernel_launch(void* const* d_in, const int* in_sizes, int n_in,
                              void* d_out, int out_size) {
    const float* x = (const float*)d_in[0];
    float* out = (float*)d_out;
    int rows  = in_sizes[0] / FRAMES;   // 32*512 = 16384
    int pairs = rows / 2;               // 8192

    constexpr int WARPS_PER_BLOCK = 4;  // 128-thread blocks -> 2048 blocks
    int blocks = (pairs + WARPS_PER_BLOCK - 1) / WARPS_PER_BLOCK;
    cumnorm_kernel<<<blocks, WARPS_PER_BLOCK * 32>>>(x, out, pairs);
}